// round 14
// baseline (speedup 1.0000x reference)
#include <cuda_runtime.h>
#include <math.h>
#include <stdint.h>

#define B_ 16
#define T_ 128
#define S_ 128
#define E_ 512
#define H_ 512
#define V_ 4096

#define TOT_CTAS 128               // 64 CTAs per layer
#define LSTM_THREADS 256
// dynamic smem: hs 32KB + xs 32KB + pr 17408
#define LSTM_SMEM (32768 + 32768 + 17408)

#define GEMM_BUF_FLOATS (128 * 20)
#define GEMM_SMEM (6 * GEMM_BUF_FLOATS * 4)   // 3-stage ring for A and B

// ---------------- scratch (device globals; no cudaMalloc allowed) -------------
__device__ float g_x[2048 * 512];        // embedded input [B*T, E]
__device__ float g_gates[2048 * 2048];   // precomputed layer0 input gates [B*T, 4H]
__device__ float g_cat[2048 * 1024];     // [y2 | context]  [B*T, H+E]
__device__ float g_encf[2048 * 512];     // enc_feat [B*S, H]
__device__ float g_decf[2048 * 512];     // dec_feat [B*T, H]
__device__ float g_ench_t[512 * 16];     // enc_hidden TRANSPOSED [k][b]
__device__ float g_h0a[512 * 16];
__device__ float g_h0b[512 * 16];
__device__ float g_h1a[512 * 16];
__device__ float g_h1b[512 * 16];
__device__ float g_y1a[512 * 16];
__device__ float g_y1b[512 * 16];
__device__ unsigned long long g_bar_cnt;

// ---------------- fast activations (single-MUFU tanh.approx) -------------------
__device__ __forceinline__ float ftanh(float x) {
    float y; asm("tanh.approx.f32 %0, %1;" : "=f"(y) : "f"(x)); return y;
}
__device__ __forceinline__ float fsig(float x) {
    return 0.5f * ftanh(0.5f * x) + 0.5f;
}

// ---------------- grid barrier (release/acquire, tight spin on tid0) ----------
__device__ __forceinline__ void grid_barrier() {
    __syncthreads();
    if (threadIdx.x == 0) {
        unsigned long long old, cur;
        asm volatile("atom.add.release.gpu.u64 %0, [%1], 1;"
                     : "=l"(old) : "l"(&g_bar_cnt) : "memory");
        unsigned long long target = (old / TOT_CTAS + 1ULL) * TOT_CTAS;
        do {
            asm volatile("ld.acquire.gpu.u64 %0, [%1];"
                         : "=l"(cur) : "l"(&g_bar_cnt) : "memory");
        } while (cur < target);
    }
    __syncthreads();
}

// ---------------- embedding gather --------------------------------------------
__global__ void k_embed(const int* __restrict__ tgt, const float* __restrict__ emb,
                        float* __restrict__ x) {
    int r = blockIdx.x;
    int tok = tgt[r];
    ((float4*)x)[r * 128 + threadIdx.x] = ((const float4*)emb)[tok * 128 + threadIdx.x];
}

// ---------------- mean over source positions (writes TRANSPOSED [e][b]) -------
__global__ void k_mean(const float* __restrict__ mem, float* __restrict__ out_t) {
    int b = blockIdx.x;
    int e = threadIdx.x;
    float s = 0.f;
    for (int t = 0; t < S_; t++) s += mem[(b * S_ + t) * 512 + e];
    out_t[e * 16 + b] = s * (1.f / (float)S_);
}

// ---------------- tf32 helpers --------------------------------------------------
__device__ __forceinline__ uint32_t f2tf32(float f) {
    uint32_t u; asm("cvt.rna.tf32.f32 %0, %1;" : "=r"(u) : "f"(f)); return u;
}
__device__ __forceinline__ void mma_tf32(float* d, const uint32_t* a, const uint32_t* b) {
    asm volatile("mma.sync.aligned.m16n8k8.row.col.f32.tf32.tf32.f32 "
        "{%0,%1,%2,%3}, {%4,%5,%6,%7}, {%8,%9}, {%0,%1,%2,%3};"
        : "+f"(d[0]), "+f"(d[1]), "+f"(d[2]), "+f"(d[3])
        : "r"(a[0]), "r"(a[1]), "r"(a[2]), "r"(a[3]), "r"(b[0]), "r"(b[1]));
}
__device__ __forceinline__ uint32_t smem_u32(const void* p) {
    uint32_t a;
    asm("{ .reg .u64 t; cvta.to.shared.u64 t, %1; cvt.u32.u64 %0, t; }"
        : "=r"(a) : "l"(p));
    return a;
}
#define CP16(dst, src) \
    asm volatile("cp.async.cg.shared.global [%0], [%1], 16;" :: "r"(dst), "l"(src))
#define CP_COMMIT() asm volatile("cp.async.commit_group;" ::: "memory")
#define CP_WAIT1()  asm volatile("cp.async.wait_group 1;" ::: "memory")
#define CP_WAIT0()  asm volatile("cp.async.wait_group 0;" ::: "memory")

// ---------------- tf32 tensor-core GEMM (cp.async 3-stage, optional accum) -----
__global__ __launch_bounds__(256, 2) void gemm_tf32(
    const float* __restrict__ A, int lda,
    const float* __restrict__ W, int ldw, int K,
    const float* __restrict__ bias1, const float* __restrict__ bias2,
    float* __restrict__ C, int ldc, int accum) {
    extern __shared__ float gshm[];
    float* As = gshm;                              // [3][GEMM_BUF_FLOATS]
    float* Bs = gshm + 3 * GEMM_BUF_FLOATS;        // [3][GEMM_BUF_FLOATS]
    const int tid = threadIdx.x;
    const int m0 = blockIdx.y * 128, n0 = blockIdx.x * 128;
    const int warp = tid >> 5, lane = tid & 31;
    const int wm = (warp & 1) * 64;
    const int wn = (warp >> 1) * 32;
    const int g = lane >> 2, c = lane & 3;

    const int lr = tid >> 2;
    const int lq = tid & 3;
    const float* Ap = A + (size_t)(m0 + lr) * lda + lq * 4;
    const float* Wp = W + (size_t)(n0 + lr) * ldw + lq * 4;
    const size_t astep = (size_t)64 * lda;
    const size_t wstep = (size_t)64 * ldw;

    const uint32_t sA0 = smem_u32(&As[lr * 20 + lq * 4]);
    const uint32_t sA1 = smem_u32(&As[(lr + 64) * 20 + lq * 4]);
    const uint32_t sB0 = smem_u32(&Bs[lr * 20 + lq * 4]);
    const uint32_t sB1 = smem_u32(&Bs[(lr + 64) * 20 + lq * 4]);
    const uint32_t bufbytes = GEMM_BUF_FLOATS * 4;

    float acc[4][4][4];
#pragma unroll
    for (int i = 0; i < 4; i++)
#pragma unroll
        for (int j = 0; j < 4; j++)
#pragma unroll
            for (int q = 0; q < 4; q++) acc[i][j][q] = 0.f;

    const int nkt = K >> 4;
    {
        CP16(sA0, Ap); CP16(sA1, Ap + astep);
        CP16(sB0, Wp); CP16(sB1, Wp + wstep);
        CP_COMMIT();
        const float* Ap2 = Ap + 16;
        const float* Wp2 = Wp + 16;
        CP16(sA0 + bufbytes, Ap2); CP16(sA1 + bufbytes, Ap2 + astep);
        CP16(sB0 + bufbytes, Wp2); CP16(sB1 + bufbytes, Wp2 + wstep);
        CP_COMMIT();
    }

    for (int kt = 0; kt < nkt; kt++) {
        if (kt + 1 < nkt) { CP_WAIT1(); } else { CP_WAIT0(); }
        __syncthreads();
        if (kt + 2 < nkt) {
            const uint32_t off = ((kt + 2) % 3) * bufbytes;
            const float* Ap2 = Ap + (kt + 2) * 16;
            const float* Wp2 = Wp + (kt + 2) * 16;
            CP16(sA0 + off, Ap2); CP16(sA1 + off, Ap2 + astep);
            CP16(sB0 + off, Wp2); CP16(sB1 + off, Wp2 + wstep);
            CP_COMMIT();
        }

        const float* Ab = As + (kt % 3) * GEMM_BUF_FLOATS;
        const float* Bb = Bs + (kt % 3) * GEMM_BUF_FLOATS;
#pragma unroll
        for (int kk = 0; kk < 16; kk += 8) {
            uint32_t af[4][4];
            uint32_t bf[4][2];
#pragma unroll
            for (int mt = 0; mt < 4; mt++) {
                int mr = wm + mt * 16 + g;
                af[mt][0] = __float_as_uint(Ab[mr * 20 + kk + c]);
                af[mt][1] = __float_as_uint(Ab[(mr + 8) * 20 + kk + c]);
                af[mt][2] = __float_as_uint(Ab[mr * 20 + kk + c + 4]);
                af[mt][3] = __float_as_uint(Ab[(mr + 8) * 20 + kk + c + 4]);
            }
#pragma unroll
            for (int nt = 0; nt < 4; nt++) {
                int nr = wn + nt * 8 + g;
                bf[nt][0] = __float_as_uint(Bb[nr * 20 + kk + c]);
                bf[nt][1] = __float_as_uint(Bb[nr * 20 + kk + c + 4]);
            }
#pragma unroll
            for (int mt = 0; mt < 4; mt++)
#pragma unroll
                for (int nt = 0; nt < 4; nt++)
                    mma_tf32(acc[mt][nt], af[mt], bf[nt]);
        }
    }

    float bv0[4], bv1[4];
#pragma unroll
    for (int nt = 0; nt < 4; nt++) {
        int col = n0 + wn + nt * 8 + 2 * c;
        float x0 = bias1 ? __ldg(&bias1[col]) : 0.f;
        float x1 = bias1 ? __ldg(&bias1[col + 1]) : 0.f;
        if (bias2) { x0 += __ldg(&bias2[col]); x1 += __ldg(&bias2[col + 1]); }
        bv0[nt] = x0; bv1[nt] = x1;
    }
#pragma unroll
    for (int mt = 0; mt < 4; mt++) {
        int r0 = m0 + wm + mt * 16 + g;
#pragma unroll
        for (int nt = 0; nt < 4; nt++) {
            int col = n0 + wn + nt * 8 + 2 * c;
            float* p0 = &C[(size_t)r0 * ldc + col];
            float* p1 = &C[(size_t)(r0 + 8) * ldc + col];
            float2 o0, o1;
            if (accum) {
                float2 c0 = *(float2*)p0;
                float2 c1 = *(float2*)p1;
                o0 = make_float2(acc[mt][nt][0] + c0.x, acc[mt][nt][1] + c0.y);
                o1 = make_float2(acc[mt][nt][2] + c1.x, acc[mt][nt][3] + c1.y);
            } else {
                o0 = make_float2(acc[mt][nt][0] + bv0[nt], acc[mt][nt][1] + bv1[nt]);
                o1 = make_float2(acc[mt][nt][2] + bv0[nt], acc[mt][nt][3] + bv1[nt]);
            }
            *(float2*)p0 = o0;
            *(float2*)p1 = o1;
        }
    }
}

// ---------------- fused 2-layer pipelined persistent LSTM ----------------------
__global__ __launch_bounds__(LSTM_THREADS, 1) void k_lstm2(
    const float* __restrict__ gates0,
    const float* __restrict__ Whh0,
    const float* __restrict__ Wih1,
    const float* __restrict__ Whh1,
    const float* __restrict__ bih1, const float* __restrict__ bhh1,
    const float* __restrict__ h_init_t,
    float* __restrict__ ycat,
    float* __restrict__ hn, float* __restrict__ cn,
    float* __restrict__ h0a, float* __restrict__ h0b,
    float* __restrict__ h1a, float* __restrict__ h1b,
    float* __restrict__ y1a, float* __restrict__ y1b) {
    extern __shared__ float smf[];
    float* hs = smf;
    float* xs = smf + 512 * 16;
    float (*pr)[32][17] = (float(*)[32][17])(smf + 2 * 512 * 16);

    const int tid = threadIdx.x;
    const int layer = blockIdx.x >> 6;
    const int bidx = blockIdx.x & 63;
    const int w = tid >> 5, lane = tid & 31;
    const int g = lane >> 2, c = lane & 3;
    const uint32_t* hsu = (const uint32_t*)hs;
    const uint32_t* xsu = (const uint32_t*)xs;
    const uint32_t hs_base = smem_u32(hs);
    const uint32_t xs_base = smem_u32(xs);

    uint32_t afr_h[2][8][4];
    uint32_t afr_x[2][8][4];
    {
        const float* Wh_ = layer ? Whh1 : Whh0;
#pragma unroll
        for (int tau = 0; tau < 2; tau++) {
            int ng0 = (g >> 2) * 512 + bidx * 8 + tau * 4 + (g & 3);
            int ng1 = ((g + 8) >> 2) * 512 + bidx * 8 + tau * 4 + (g & 3);
            const float* w0 = Wh_ + (size_t)ng0 * 512;
            const float* w1 = Wh_ + (size_t)ng1 * 512;
#pragma unroll
            for (int kc = 0; kc < 8; kc++) {
                int kb = w * 64 + kc * 8;
                afr_h[tau][kc][0] = f2tf32(__ldg(w0 + kb + c));
                afr_h[tau][kc][1] = f2tf32(__ldg(w1 + kb + c));
                afr_h[tau][kc][2] = f2tf32(__ldg(w0 + kb + c + 4));
                afr_h[tau][kc][3] = f2tf32(__ldg(w1 + kb + c + 4));
            }
            if (layer) {
                const float* x0 = Wih1 + (size_t)ng0 * 512;
                const float* x1 = Wih1 + (size_t)ng1 * 512;
#pragma unroll
                for (int kc = 0; kc < 8; kc++) {
                    int kb = w * 64 + kc * 8;
                    afr_x[tau][kc][0] = f2tf32(__ldg(x0 + kb + c));
                    afr_x[tau][kc][1] = f2tf32(__ldg(x1 + kb + c));
                    afr_x[tau][kc][2] = f2tf32(__ldg(x0 + kb + c + 4));
                    afr_x[tau][kc][3] = f2tf32(__ldg(x1 + kb + c + 4));
                }
            }
        }
    }

    float c_reg = 0.f;
    const int cb = tid & 15, hloc = (tid >> 4) & 7;
    const int kh = bidx * 8 + hloc;
    const int ctau = hloc >> 2, cr = hloc & 3;
    float gp[4] = {0.f, 0.f, 0.f, 0.f};
    if (tid < 128) {
        if (layer) {
#pragma unroll
            for (int g4 = 0; g4 < 4; g4++)
                gp[g4] = __ldg(&bih1[g4 * 512 + kh]) + __ldg(&bhh1[g4 * 512 + kh]);
        } else {
            const float* gpr = gates0 + ((size_t)(cb * T_)) * 2048 + kh;
#pragma unroll
            for (int g4 = 0; g4 < 4; g4++)
                gp[g4] = __ldg(gpr + g4 * 512);
        }
    }

    grid_barrier();

    for (int s = 0; s <= T_; s++) {
        const int t = layer ? (s - 1) : s;
        const bool active = layer ? (s >= 1) : (s < T_);
        if (active) {
            const float* hin;
            float* hout;
            if (layer == 0) {
                hin  = (t == 0) ? h_init_t : ((t & 1) ? h0a : h0b);
                hout = (t & 1) ? h0b : h0a;
            } else {
                hin  = (t == 0) ? h_init_t : ((t & 1) ? h1a : h1b);
                hout = (t & 1) ? h1b : h1a;
            }
            const float* xin = (t & 1) ? y1b : y1a;
            float* yout = (t & 1) ? y1b : y1a;

#pragma unroll
            for (int i = 0; i < 8; i++) {
                int idx = tid + 256 * i;
                CP16(hs_base + idx * 16, ((const float4*)hin) + idx);
            }
            if (layer) {
#pragma unroll
                for (int i = 0; i < 8; i++) {
                    int idx = tid + 256 * i;
                    CP16(xs_base + idx * 16, ((const float4*)xin) + idx);
                }
            }
            CP_COMMIT();
            CP_WAIT0();
            __syncthreads();

            float acc[2][2][4];
#pragma unroll
            for (int a = 0; a < 2; a++)
#pragma unroll
                for (int b = 0; b < 2; b++)
#pragma unroll
                    for (int q = 0; q < 4; q++) acc[a][b][q] = 0.f;

#pragma unroll
            for (int kc = 0; kc < 8; kc++) {
                int kb = w * 64 + kc * 8;
                uint32_t b0[2], b1[2];
                b0[0] = hsu[(kb + c) * 16 + g];
                b0[1] = hsu[(kb + c + 4) * 16 + g];
                b1[0] = hsu[(kb + c) * 16 + 8 + g];
                b1[1] = hsu[(kb + c + 4) * 16 + 8 + g];
                mma_tf32(acc[0][0], afr_h[0][kc], b0);
                mma_tf32(acc[0][1], afr_h[0][kc], b1);
                mma_tf32(acc[1][0], afr_h[1][kc], b0);
                mma_tf32(acc[1][1], afr_h[1][kc], b1);
            }
            if (layer) {
#pragma unroll
                for (int kc = 0; kc < 8; kc++) {
                    int kb = w * 64 + kc * 8;
                    uint32_t b0[2], b1[2];
                    b0[0] = xsu[(kb + c) * 16 + g];
                    b0[1] = xsu[(kb + c + 4) * 16 + g];
                    b1[0] = xsu[(kb + c) * 16 + 8 + g];
                    b1[1] = xsu[(kb + c + 4) * 16 + 8 + g];
                    mma_tf32(acc[0][0], afr_x[0][kc], b0);
                    mma_tf32(acc[0][1], afr_x[0][kc], b1);
                    mma_tf32(acc[1][0], afr_x[1][kc], b0);
                    mma_tf32(acc[1][1], afr_x[1][kc], b1);
                }
            }
#pragma unroll
            for (int tau = 0; tau < 2; tau++) {
                pr[w][tau * 16 + g][2 * c]         = acc[tau][0][0];
                pr[w][tau * 16 + g][2 * c + 1]     = acc[tau][0][1];
                pr[w][tau * 16 + g + 8][2 * c]     = acc[tau][0][2];
                pr[w][tau * 16 + g + 8][2 * c + 1] = acc[tau][0][3];
                pr[w][tau * 16 + g][8 + 2 * c]         = acc[tau][1][0];
                pr[w][tau * 16 + g][8 + 2 * c + 1]     = acc[tau][1][1];
                pr[w][tau * 16 + g + 8][8 + 2 * c]     = acc[tau][1][2];
                pr[w][tau * 16 + g + 8][8 + 2 * c + 1] = acc[tau][1][3];
            }
            __syncthreads();

            if (tid < 128) {
                float sg[4];
#pragma unroll
                for (int g4 = 0; g4 < 4; g4++) {
                    float a = gp[g4];
                    int row = ctau * 16 + g4 * 4 + cr;
#pragma unroll
                    for (int q = 0; q < 8; q++) a += pr[q][row][cb];
                    sg[g4] = a;
                }
                float iv = fsig(sg[0]);
                float fv = fsig(sg[1]);
                float gv = ftanh(sg[2]);
                float ov = fsig(sg[3]);
                c_reg = fv * c_reg + iv * gv;
                float hv = ov * ftanh(c_reg);
                hout[kh * 16 + cb] = hv;
                if (layer == 0) {
                    yout[kh * 16 + cb] = hv;
                    if (t == T_ - 1) {
                        hn[cb * 512 + kh] = hv;
                        cn[cb * 512 + kh] = c_reg;
                    }
                    if (t + 1 < T_) {
                        const float* gpr = gates0 + ((size_t)(cb * T_ + t + 1)) * 2048 + kh;
#pragma unroll
                        for (int g4 = 0; g4 < 4; g4++)
                            gp[g4] = __ldg(gpr + g4 * 512);
                    }
                } else {
                    ycat[((size_t)(cb * T_ + t)) * 1024 + kh] = hv;
                    if (t == T_ - 1) {
                        hn[B_ * H_ + cb * 512 + kh] = hv;
                        cn[B_ * H_ + cb * 512 + kh] = c_reg;
                    }
                }
            }
        }
        grid_barrier();
    }
}

// ---------------- fused attention (prefetch-pipelined row staging) -------------
__global__ __launch_bounds__(256) void k_attn(
    const float* __restrict__ encf, const float* __restrict__ decf,
    const float* __restrict__ mem, const unsigned char* __restrict__ mask,
    const float* __restrict__ v, const float* __restrict__ vb,
    float* __restrict__ outcat) {
    __shared__ float df[8][512];
    __shared__ float vsh[512];
    __shared__ float row[512];
    __shared__ float en[8][128];
    const int b = blockIdx.x;
    const int t0 = blockIdx.y * 8;
    const int tid = threadIdx.x;
    const int w = tid >> 5, lane = tid & 31;

    for (int i = tid; i < 512; i += 256) vsh[i] = v[i];
    for (int i = tid; i < 8 * 512; i += 256) {
        int jj = i >> 9, h = i & 511;
        df[jj][h] = decf[((size_t)(b * T_ + t0 + jj)) * 512 + h];
    }
    __syncthreads();
    const float vbv = vb[0];

    {
        const float* ebase = encf + (size_t)(b * S_) * 512;
        float p0 = __ldg(ebase + tid);
        float p1 = __ldg(ebase + tid + 256);
        for (int s = 0; s < S_; s++) {
            row[tid] = p0;
            row[tid + 256] = p1;
            __syncthreads();
            if (s + 1 < S_) {
                p0 = __ldg(ebase + (size_t)(s + 1) * 512 + tid);
                p1 = __ldg(ebase + (size_t)(s + 1) * 512 + tid + 256);
            }
            float e = 0.f;
#pragma unroll
            for (int i = 0; i < 16; i++) {
                int h = lane + 32 * i;
                e = fmaf(vsh[h], ftanh(row[h] + df[w][h]), e);
            }
#pragma unroll
            for (int off = 16; off; off >>= 1) e += __shfl_xor_sync(0xffffffffu, e, off);
            if (lane == 0) {
                e += vbv;
                if (mask[b * S_ + s]) e = -1e9f;
                en[w][s] = e;
            }
            __syncthreads();
        }
    }

    {
        float vals[4];
        float m = -1e30f;
#pragma unroll
        for (int i = 0; i < 4; i++) { vals[i] = en[w][lane + 32 * i]; m = fmaxf(m, vals[i]); }
#pragma unroll
        for (int off = 16; off; off >>= 1) m = fmaxf(m, __shfl_xor_sync(0xffffffffu, m, off));
        float ssum = 0.f;
#pragma unroll
        for (int i = 0; i < 4; i++) { vals[i] = __expf(vals[i] - m); ssum += vals[i]; }
#pragma unroll
        for (int off = 16; off; off >>= 1) ssum += __shfl_xor_sync(0xffffffffu, ssum, off);
        float inv = 1.f / ssum;
#pragma unroll
        for (int i = 0; i < 4; i++) en[w][lane + 32 * i] = vals[i] * inv;
    }
    __syncthreads();

    float c0[8], c1[8];
#pragma unroll
    for (int jj = 0; jj < 8; jj++) { c0[jj] = 0.f; c1[jj] = 0.f; }
    {
        const float* mbase = mem + (size_t)(b * S_) * 512;
        float q0 = __ldg(mbase + tid);
        float q1 = __ldg(mbase + tid + 256);
        for (int s = 0; s < S_; s++) {
            row[tid] = q0;
            row[tid + 256] = q1;
            __syncthreads();
            if (s + 1 < S_) {
                q0 = __ldg(mbase + (size_t)(s + 1) * 512 + tid);
                q1 = __ldg(mbase + (size_t)(s + 1) * 512 + tid + 256);
            }
            float m0 = row[tid], m1 = row[tid + 256];
#pragma unroll
            for (int jj = 0; jj < 8; jj++) {
                float a = en[jj][s];
                c0[jj] = fmaf(a, m0, c0[jj]);
                c1[jj] = fmaf(a, m1, c1[jj]);
            }
            __syncthreads();
        }
    }
#pragma unroll
    for (int jj = 0; jj < 8; jj++) {
        size_t rr = ((size_t)(b * T_ + t0 + jj)) * 1024 + 512;
        outcat[rr + tid] = c0[jj];
        outcat[rr + tid + 256] = c1[jj];
    }
}

// ---------------- launch -------------------------------------------------------
extern "C" void kernel_launch(void* const* d_in, const int* in_sizes, int n_in,
                              void* d_out, int out_size) {
    (void)in_sizes; (void)n_in; (void)out_size;
    const int*   tgt  = (const int*)d_in[0];
    const float* mem  = (const float*)d_in[1];
    const unsigned char* mask = (const unsigned char*)d_in[2];
    const float* emb  = (const float*)d_in[3];
    const float* Wih0 = (const float*)d_in[4];
    const float* Whh0 = (const float*)d_in[5];
    const float* bih0 = (const float*)d_in[6];
    const float* bhh0 = (const float*)d_in[7];
    const float* Wih1 = (const float*)d_in[8];
    const float* Whh1 = (const float*)d_in[9];
    const float* bih1 = (const float*)d_in[10];
    const float* bhh1 = (const float*)d_in[11];
    const float* Wh   = (const float*)d_in[12];
    const float* bh   = (const float*)d_in[13];
    const float* Ws   = (const float*)d_in[14];
    const float* bs   = (const float*)d_in[15];
    const float* v    = (const float*)d_in[16];
    const float* vb   = (const float*)d_in[17];
    const float* Wout = (const float*)d_in[18];
    const float* bout = (const float*)d_in[19];

    float* out = (float*)d_out;
    float* logits = out;
    float* hn = out + (size_t)B_ * T_ * V_;
    float* cn = hn + 2 * B_ * H_;

    float *px, *pgates, *pcat, *pencf, *pdecf, *pench;
    float *ph0a, *ph0b, *ph1a, *ph1b, *py1a, *py1b;
    cudaGetSymbolAddress((void**)&px, g_x);
    cudaGetSymbolAddress((void**)&pgates, g_gates);
    cudaGetSymbolAddress((void**)&pcat, g_cat);
    cudaGetSymbolAddress((void**)&pencf, g_encf);
    cudaGetSymbolAddress((void**)&pdecf, g_decf);
    cudaGetSymbolAddress((void**)&pench, g_ench_t);
    cudaGetSymbolAddress((void**)&ph0a, g_h0a);
    cudaGetSymbolAddress((void**)&ph0b, g_h0b);
    cudaGetSymbolAddress((void**)&ph1a, g_h1a);
    cudaGetSymbolAddress((void**)&ph1b, g_h1b);
    cudaGetSymbolAddress((void**)&py1a, g_y1a);
    cudaGetSymbolAddress((void**)&py1b, g_y1b);

    cudaFuncSetAttribute(k_lstm2, cudaFuncAttributeMaxDynamicSharedMemorySize, LSTM_SMEM);
    cudaFuncSetAttribute(gemm_tf32, cudaFuncAttributeMaxDynamicSharedMemorySize, GEMM_SMEM);

    // second stream + events for overlap (leaked; not device memory)
    cudaStream_t s2;
    cudaStreamCreateWithFlags(&s2, cudaStreamNonBlocking);
    cudaEvent_t eFork, eEncf, eLstm, eY2;
    cudaEventCreateWithFlags(&eFork, cudaEventDisableTiming);
    cudaEventCreateWithFlags(&eEncf, cudaEventDisableTiming);
    cudaEventCreateWithFlags(&eLstm, cudaEventDisableTiming);
    cudaEventCreateWithFlags(&eY2, cudaEventDisableTiming);

    // fork s2 from the origin stream
    cudaEventRecord(eFork, 0);
    cudaStreamWaitEvent(s2, eFork, 0);

    // s2: encf (independent of everything except input mem)
    gemm_tf32<<<dim3(4, 16), 256, GEMM_SMEM, s2>>>(mem, 512, Wh, 512, 512,
                                                   bh, nullptr, pencf, 512, 0);
    cudaEventRecord(eEncf, s2);

    // main stream: embed, mean, gates0, LSTM
    k_embed<<<2048, 128>>>(tgt, emb, px);
    k_mean<<<B_, 512>>>(mem, pench);
    gemm_tf32<<<dim3(16, 16), 256, GEMM_SMEM>>>(px, 512, Wih0, 512, 512,
                                                bih0, bhh0, pgates, 2048, 0);
    k_lstm2<<<TOT_CTAS, LSTM_THREADS, LSTM_SMEM>>>(
        pgates, Whh0, Wih1, Whh1, bih1, bhh1, pench,
        pcat, hn, cn, ph0a, ph0b, ph1a, ph1b, py1a, py1b);
    cudaEventRecord(eLstm, 0);

    // s2: y2-half of logits (C = y2 @ Wout[:, :512]^T + bout), overlapped with attn
    cudaStreamWaitEvent(s2, eLstm, 0);
    gemm_tf32<<<dim3(32, 16), 256, GEMM_SMEM, s2>>>(pcat, 1024, Wout, 1024, 512,
                                                    bout, nullptr, logits, 4096, 0);
    cudaEventRecord(eY2, s2);

    // main stream: decf, attn (needs encf), then ctx-half accumulate
    gemm_tf32<<<dim3(4, 16), 256, GEMM_SMEM>>>(pcat, 1024, Ws, 512, 512,
                                               bs, nullptr, pdecf, 512, 0);
    cudaStreamWaitEvent(0, eEncf, 0);
    k_attn<<<dim3(B_, T_ / 8), 256>>>(pencf, pdecf, mem, mask, v, vb, pcat);

    cudaStreamWaitEvent(0, eY2, 0);
    gemm_tf32<<<dim3(32, 16), 256, GEMM_SMEM>>>(pcat + 512, 1024, Wout + 512, 1024, 512,
                                                nullptr, nullptr, logits, 4096, 1);
}

// round 15
// speedup vs baseline: 1.2629x; 1.2629x over previous
#include <cuda_runtime.h>
#include <math.h>
#include <stdint.h>

#define B_ 16
#define T_ 128
#define S_ 128
#define E_ 512
#define H_ 512
#define V_ 4096

#define TOT_CTAS 128               // 64 CTAs per layer
#define LSTM_THREADS 256
// dynamic smem: hs 32KB + xs 32KB + pr 17408
#define LSTM_SMEM (32768 + 32768 + 17408)

#define GEMM_BUF_FLOATS (128 * 20)
#define GEMM_SMEM (6 * GEMM_BUF_FLOATS * 4)   // 3-stage ring for A and B

// ---------------- scratch (device globals; no cudaMalloc allowed) -------------
__device__ float g_x[2048 * 512];        // embedded input [B*T, E]
__device__ float g_gates[2048 * 2048];   // precomputed layer0 input gates [B*T, 4H]
__device__ float g_cat[2048 * 1024];     // [y2 | context]  [B*T, H+E]
__device__ float g_encf[2048 * 512];     // enc_feat [B*S, H]
__device__ float g_decf[2048 * 512];     // dec_feat [B*T, H]
__device__ float g_ench_t[512 * 16];     // enc_hidden TRANSPOSED [k][b]
__device__ float g_h0a[512 * 16];
__device__ float g_h0b[512 * 16];
__device__ float g_h1a[512 * 16];
__device__ float g_h1b[512 * 16];
__device__ float g_y1a[512 * 16];
__device__ float g_y1b[512 * 16];
__device__ unsigned long long g_bar_cnt;

// ---------------- fast activations (single-MUFU tanh.approx) -------------------
__device__ __forceinline__ float ftanh(float x) {
    float y; asm("tanh.approx.f32 %0, %1;" : "=f"(y) : "f"(x)); return y;
}
__device__ __forceinline__ float fsig(float x) {
    return 0.5f * ftanh(0.5f * x) + 0.5f;
}

// ---------------- grid barrier (release/acquire, tight spin on tid0) ----------
__device__ __forceinline__ void grid_barrier() {
    __syncthreads();
    if (threadIdx.x == 0) {
        unsigned long long old, cur;
        asm volatile("atom.add.release.gpu.u64 %0, [%1], 1;"
                     : "=l"(old) : "l"(&g_bar_cnt) : "memory");
        unsigned long long target = (old / TOT_CTAS + 1ULL) * TOT_CTAS;
        do {
            asm volatile("ld.acquire.gpu.u64 %0, [%1];"
                         : "=l"(cur) : "l"(&g_bar_cnt) : "memory");
        } while (cur < target);
    }
    __syncthreads();
}

// ---------------- embedding gather --------------------------------------------
__global__ void k_embed(const int* __restrict__ tgt, const float* __restrict__ emb,
                        float* __restrict__ x) {
    int r = blockIdx.x;
    int tok = tgt[r];
    ((float4*)x)[r * 128 + threadIdx.x] = ((const float4*)emb)[tok * 128 + threadIdx.x];
}

// ---------------- mean over source positions (writes TRANSPOSED [e][b]) -------
__global__ void k_mean(const float* __restrict__ mem, float* __restrict__ out_t) {
    int b = blockIdx.x;
    int e = threadIdx.x;
    float s = 0.f;
    for (int t = 0; t < S_; t++) s += mem[(b * S_ + t) * 512 + e];
    out_t[e * 16 + b] = s * (1.f / (float)S_);
}

// ---------------- tf32 helpers --------------------------------------------------
__device__ __forceinline__ uint32_t f2tf32(float f) {
    uint32_t u; asm("cvt.rna.tf32.f32 %0, %1;" : "=r"(u) : "f"(f)); return u;
}
__device__ __forceinline__ void mma_tf32(float* d, const uint32_t* a, const uint32_t* b) {
    asm volatile("mma.sync.aligned.m16n8k8.row.col.f32.tf32.tf32.f32 "
        "{%0,%1,%2,%3}, {%4,%5,%6,%7}, {%8,%9}, {%0,%1,%2,%3};"
        : "+f"(d[0]), "+f"(d[1]), "+f"(d[2]), "+f"(d[3])
        : "r"(a[0]), "r"(a[1]), "r"(a[2]), "r"(a[3]), "r"(b[0]), "r"(b[1]));
}
__device__ __forceinline__ uint32_t smem_u32(const void* p) {
    uint32_t a;
    asm("{ .reg .u64 t; cvta.to.shared.u64 t, %1; cvt.u32.u64 %0, t; }"
        : "=r"(a) : "l"(p));
    return a;
}
#define CP16(dst, src) \
    asm volatile("cp.async.cg.shared.global [%0], [%1], 16;" :: "r"(dst), "l"(src))
#define CP_COMMIT() asm volatile("cp.async.commit_group;" ::: "memory")
#define CP_WAIT1()  asm volatile("cp.async.wait_group 1;" ::: "memory")
#define CP_WAIT0()  asm volatile("cp.async.wait_group 0;" ::: "memory")

// ---------------- tf32 tensor-core GEMM (cp.async 3-stage, 1 sync/iter) --------
__global__ __launch_bounds__(256, 2) void gemm_tf32(
    const float* __restrict__ A, int lda,
    const float* __restrict__ W, int ldw, int K,
    const float* __restrict__ bias1, const float* __restrict__ bias2,
    float* __restrict__ C, int ldc) {
    extern __shared__ float gshm[];
    float* As = gshm;                              // [3][GEMM_BUF_FLOATS]
    float* Bs = gshm + 3 * GEMM_BUF_FLOATS;        // [3][GEMM_BUF_FLOATS]
    const int tid = threadIdx.x;
    const int m0 = blockIdx.y * 128, n0 = blockIdx.x * 128;
    const int warp = tid >> 5, lane = tid & 31;
    const int wm = (warp & 1) * 64;
    const int wn = (warp >> 1) * 32;
    const int g = lane >> 2, c = lane & 3;

    const int lr = tid >> 2;
    const int lq = tid & 3;
    const float* Ap = A + (size_t)(m0 + lr) * lda + lq * 4;
    const float* Wp = W + (size_t)(n0 + lr) * ldw + lq * 4;
    const size_t astep = (size_t)64 * lda;
    const size_t wstep = (size_t)64 * ldw;

    const uint32_t sA0 = smem_u32(&As[lr * 20 + lq * 4]);
    const uint32_t sA1 = smem_u32(&As[(lr + 64) * 20 + lq * 4]);
    const uint32_t sB0 = smem_u32(&Bs[lr * 20 + lq * 4]);
    const uint32_t sB1 = smem_u32(&Bs[(lr + 64) * 20 + lq * 4]);
    const uint32_t bufbytes = GEMM_BUF_FLOATS * 4;

    float acc[4][4][4];
#pragma unroll
    for (int i = 0; i < 4; i++)
#pragma unroll
        for (int j = 0; j < 4; j++)
#pragma unroll
            for (int q = 0; q < 4; q++) acc[i][j][q] = 0.f;

    const int nkt = K >> 4;
    {
        CP16(sA0, Ap); CP16(sA1, Ap + astep);
        CP16(sB0, Wp); CP16(sB1, Wp + wstep);
        CP_COMMIT();
        const float* Ap2 = Ap + 16;
        const float* Wp2 = Wp + 16;
        CP16(sA0 + bufbytes, Ap2); CP16(sA1 + bufbytes, Ap2 + astep);
        CP16(sB0 + bufbytes, Wp2); CP16(sB1 + bufbytes, Wp2 + wstep);
        CP_COMMIT();
    }

    for (int kt = 0; kt < nkt; kt++) {
        if (kt + 1 < nkt) { CP_WAIT1(); } else { CP_WAIT0(); }
        __syncthreads();
        if (kt + 2 < nkt) {
            const uint32_t off = ((kt + 2) % 3) * bufbytes;
            const float* Ap2 = Ap + (kt + 2) * 16;
            const float* Wp2 = Wp + (kt + 2) * 16;
            CP16(sA0 + off, Ap2); CP16(sA1 + off, Ap2 + astep);
            CP16(sB0 + off, Wp2); CP16(sB1 + off, Wp2 + wstep);
            CP_COMMIT();
        }

        const float* Ab = As + (kt % 3) * GEMM_BUF_FLOATS;
        const float* Bb = Bs + (kt % 3) * GEMM_BUF_FLOATS;
#pragma unroll
        for (int kk = 0; kk < 16; kk += 8) {
            uint32_t af[4][4];
            uint32_t bf[4][2];
#pragma unroll
            for (int mt = 0; mt < 4; mt++) {
                int mr = wm + mt * 16 + g;
                af[mt][0] = __float_as_uint(Ab[mr * 20 + kk + c]);
                af[mt][1] = __float_as_uint(Ab[(mr + 8) * 20 + kk + c]);
                af[mt][2] = __float_as_uint(Ab[mr * 20 + kk + c + 4]);
                af[mt][3] = __float_as_uint(Ab[(mr + 8) * 20 + kk + c + 4]);
            }
#pragma unroll
            for (int nt = 0; nt < 4; nt++) {
                int nr = wn + nt * 8 + g;
                bf[nt][0] = __float_as_uint(Bb[nr * 20 + kk + c]);
                bf[nt][1] = __float_as_uint(Bb[nr * 20 + kk + c + 4]);
            }
#pragma unroll
            for (int mt = 0; mt < 4; mt++)
#pragma unroll
                for (int nt = 0; nt < 4; nt++)
                    mma_tf32(acc[mt][nt], af[mt], bf[nt]);
        }
    }

    float bv0[4], bv1[4];
#pragma unroll
    for (int nt = 0; nt < 4; nt++) {
        int col = n0 + wn + nt * 8 + 2 * c;
        float x0 = bias1 ? __ldg(&bias1[col]) : 0.f;
        float x1 = bias1 ? __ldg(&bias1[col + 1]) : 0.f;
        if (bias2) { x0 += __ldg(&bias2[col]); x1 += __ldg(&bias2[col + 1]); }
        bv0[nt] = x0; bv1[nt] = x1;
    }
#pragma unroll
    for (int mt = 0; mt < 4; mt++) {
        int r0 = m0 + wm + mt * 16 + g;
#pragma unroll
        for (int nt = 0; nt < 4; nt++) {
            int col = n0 + wn + nt * 8 + 2 * c;
            float2 o0 = make_float2(acc[mt][nt][0] + bv0[nt], acc[mt][nt][1] + bv1[nt]);
            float2 o1 = make_float2(acc[mt][nt][2] + bv0[nt], acc[mt][nt][3] + bv1[nt]);
            *(float2*)&C[(size_t)r0 * ldc + col] = o0;
            *(float2*)&C[(size_t)(r0 + 8) * ldc + col] = o1;
        }
    }
}

// ---------------- fused 2-layer pipelined persistent LSTM ----------------------
__global__ __launch_bounds__(LSTM_THREADS, 1) void k_lstm2(
    const float* __restrict__ gates0,
    const float* __restrict__ Whh0,
    const float* __restrict__ Wih1,
    const float* __restrict__ Whh1,
    const float* __restrict__ bih1, const float* __restrict__ bhh1,
    const float* __restrict__ h_init_t,
    float* __restrict__ ycat,
    float* __restrict__ hn, float* __restrict__ cn,
    float* __restrict__ h0a, float* __restrict__ h0b,
    float* __restrict__ h1a, float* __restrict__ h1b,
    float* __restrict__ y1a, float* __restrict__ y1b) {
    extern __shared__ float smf[];
    float* hs = smf;
    float* xs = smf + 512 * 16;
    float (*pr)[32][17] = (float(*)[32][17])(smf + 2 * 512 * 16);

    const int tid = threadIdx.x;
    const int layer = blockIdx.x >> 6;
    const int bidx = blockIdx.x & 63;
    const int w = tid >> 5, lane = tid & 31;
    const int g = lane >> 2, c = lane & 3;
    const uint32_t* hsu = (const uint32_t*)hs;
    const uint32_t* xsu = (const uint32_t*)xs;
    const uint32_t hs_base = smem_u32(hs);
    const uint32_t xs_base = smem_u32(xs);

    uint32_t afr_h[2][8][4];
    uint32_t afr_x[2][8][4];
    {
        const float* Wh_ = layer ? Whh1 : Whh0;
#pragma unroll
        for (int tau = 0; tau < 2; tau++) {
            int ng0 = (g >> 2) * 512 + bidx * 8 + tau * 4 + (g & 3);
            int ng1 = ((g + 8) >> 2) * 512 + bidx * 8 + tau * 4 + (g & 3);
            const float* w0 = Wh_ + (size_t)ng0 * 512;
            const float* w1 = Wh_ + (size_t)ng1 * 512;
#pragma unroll
            for (int kc = 0; kc < 8; kc++) {
                int kb = w * 64 + kc * 8;
                afr_h[tau][kc][0] = f2tf32(__ldg(w0 + kb + c));
                afr_h[tau][kc][1] = f2tf32(__ldg(w1 + kb + c));
                afr_h[tau][kc][2] = f2tf32(__ldg(w0 + kb + c + 4));
                afr_h[tau][kc][3] = f2tf32(__ldg(w1 + kb + c + 4));
            }
            if (layer) {
                const float* x0 = Wih1 + (size_t)ng0 * 512;
                const float* x1 = Wih1 + (size_t)ng1 * 512;
#pragma unroll
                for (int kc = 0; kc < 8; kc++) {
                    int kb = w * 64 + kc * 8;
                    afr_x[tau][kc][0] = f2tf32(__ldg(x0 + kb + c));
                    afr_x[tau][kc][1] = f2tf32(__ldg(x1 + kb + c));
                    afr_x[tau][kc][2] = f2tf32(__ldg(x0 + kb + c + 4));
                    afr_x[tau][kc][3] = f2tf32(__ldg(x1 + kb + c + 4));
                }
            }
        }
    }

    float c_reg = 0.f;
    const int cb = tid & 15, hloc = (tid >> 4) & 7;
    const int kh = bidx * 8 + hloc;
    const int ctau = hloc >> 2, cr = hloc & 3;
    float gp[4] = {0.f, 0.f, 0.f, 0.f};
    if (tid < 128) {
        if (layer) {
#pragma unroll
            for (int g4 = 0; g4 < 4; g4++)
                gp[g4] = __ldg(&bih1[g4 * 512 + kh]) + __ldg(&bhh1[g4 * 512 + kh]);
        } else {
            const float* gpr = gates0 + ((size_t)(cb * T_)) * 2048 + kh;
#pragma unroll
            for (int g4 = 0; g4 < 4; g4++)
                gp[g4] = __ldg(gpr + g4 * 512);
        }
    }

    grid_barrier();

    for (int s = 0; s <= T_; s++) {
        const int t = layer ? (s - 1) : s;
        const bool active = layer ? (s >= 1) : (s < T_);
        if (active) {
            const float* hin;
            float* hout;
            if (layer == 0) {
                hin  = (t == 0) ? h_init_t : ((t & 1) ? h0a : h0b);
                hout = (t & 1) ? h0b : h0a;
            } else {
                hin  = (t == 0) ? h_init_t : ((t & 1) ? h1a : h1b);
                hout = (t & 1) ? h1b : h1a;
            }
            const float* xin = (t & 1) ? y1b : y1a;
            float* yout = (t & 1) ? y1b : y1a;

#pragma unroll
            for (int i = 0; i < 8; i++) {
                int idx = tid + 256 * i;
                CP16(hs_base + idx * 16, ((const float4*)hin) + idx);
            }
            if (layer) {
#pragma unroll
                for (int i = 0; i < 8; i++) {
                    int idx = tid + 256 * i;
                    CP16(xs_base + idx * 16, ((const float4*)xin) + idx);
                }
            }
            CP_COMMIT();
            CP_WAIT0();
            __syncthreads();

            float acc[2][2][4];
#pragma unroll
            for (int a = 0; a < 2; a++)
#pragma unroll
                for (int b = 0; b < 2; b++)
#pragma unroll
                    for (int q = 0; q < 4; q++) acc[a][b][q] = 0.f;

#pragma unroll
            for (int kc = 0; kc < 8; kc++) {
                int kb = w * 64 + kc * 8;
                uint32_t b0[2], b1[2];
                b0[0] = hsu[(kb + c) * 16 + g];
                b0[1] = hsu[(kb + c + 4) * 16 + g];
                b1[0] = hsu[(kb + c) * 16 + 8 + g];
                b1[1] = hsu[(kb + c + 4) * 16 + 8 + g];
                mma_tf32(acc[0][0], afr_h[0][kc], b0);
                mma_tf32(acc[0][1], afr_h[0][kc], b1);
                mma_tf32(acc[1][0], afr_h[1][kc], b0);
                mma_tf32(acc[1][1], afr_h[1][kc], b1);
            }
            if (layer) {
#pragma unroll
                for (int kc = 0; kc < 8; kc++) {
                    int kb = w * 64 + kc * 8;
                    uint32_t b0[2], b1[2];
                    b0[0] = xsu[(kb + c) * 16 + g];
                    b0[1] = xsu[(kb + c + 4) * 16 + g];
                    b1[0] = xsu[(kb + c) * 16 + 8 + g];
                    b1[1] = xsu[(kb + c + 4) * 16 + 8 + g];
                    mma_tf32(acc[0][0], afr_x[0][kc], b0);
                    mma_tf32(acc[0][1], afr_x[0][kc], b1);
                    mma_tf32(acc[1][0], afr_x[1][kc], b0);
                    mma_tf32(acc[1][1], afr_x[1][kc], b1);
                }
            }
#pragma unroll
            for (int tau = 0; tau < 2; tau++) {
                pr[w][tau * 16 + g][2 * c]         = acc[tau][0][0];
                pr[w][tau * 16 + g][2 * c + 1]     = acc[tau][0][1];
                pr[w][tau * 16 + g + 8][2 * c]     = acc[tau][0][2];
                pr[w][tau * 16 + g + 8][2 * c + 1] = acc[tau][0][3];
                pr[w][tau * 16 + g][8 + 2 * c]         = acc[tau][1][0];
                pr[w][tau * 16 + g][8 + 2 * c + 1]     = acc[tau][1][1];
                pr[w][tau * 16 + g + 8][8 + 2 * c]     = acc[tau][1][2];
                pr[w][tau * 16 + g + 8][8 + 2 * c + 1] = acc[tau][1][3];
            }
            __syncthreads();

            if (tid < 128) {
                float sg[4];
#pragma unroll
                for (int g4 = 0; g4 < 4; g4++) {
                    float a = gp[g4];
                    int row = ctau * 16 + g4 * 4 + cr;
#pragma unroll
                    for (int q = 0; q < 8; q++) a += pr[q][row][cb];
                    sg[g4] = a;
                }
                float iv = fsig(sg[0]);
                float fv = fsig(sg[1]);
                float gv = ftanh(sg[2]);
                float ov = fsig(sg[3]);
                c_reg = fv * c_reg + iv * gv;
                float hv = ov * ftanh(c_reg);
                hout[kh * 16 + cb] = hv;
                if (layer == 0) {
                    yout[kh * 16 + cb] = hv;
                    if (t == T_ - 1) {
                        hn[cb * 512 + kh] = hv;
                        cn[cb * 512 + kh] = c_reg;
                    }
                    if (t + 1 < T_) {
                        const float* gpr = gates0 + ((size_t)(cb * T_ + t + 1)) * 2048 + kh;
#pragma unroll
                        for (int g4 = 0; g4 < 4; g4++)
                            gp[g4] = __ldg(gpr + g4 * 512);
                    }
                } else {
                    ycat[((size_t)(cb * T_ + t)) * 1024 + kh] = hv;
                    if (t == T_ - 1) {
                        hn[B_ * H_ + cb * 512 + kh] = hv;
                        cn[B_ * H_ + cb * 512 + kh] = c_reg;
                    }
                }
            }
        }
        grid_barrier();
    }
}

// ---------------- fused attention (t-tile 16, 512 threads, prefetch rows) ------
__global__ __launch_bounds__(512) void k_attn(
    const float* __restrict__ encf, const float* __restrict__ decf,
    const float* __restrict__ mem, const unsigned char* __restrict__ mask,
    const float* __restrict__ v, const float* __restrict__ vb,
    float* __restrict__ outcat) {
    __shared__ float df[16][512];
    __shared__ float vsh[512];
    __shared__ float row[512];
    __shared__ float en[16][128];
    const int b = blockIdx.x;
    const int t0 = blockIdx.y * 16;
    const int tid = threadIdx.x;
    const int w = tid >> 5, lane = tid & 31;

    for (int i = tid; i < 512; i += 512) vsh[i] = v[i];
    for (int i = tid; i < 16 * 512; i += 512) {
        int jj = i >> 9, h = i & 511;
        df[jj][h] = decf[((size_t)(b * T_ + t0 + jj)) * 512 + h];
    }
    __syncthreads();
    const float vbv = vb[0];

    // phase 1: energies (warp w handles t0+w; 512 threads stage one row)
    {
        const float* ebase = encf + (size_t)(b * S_) * 512;
        float p0 = __ldg(ebase + tid);
        for (int s = 0; s < S_; s++) {
            row[tid] = p0;
            __syncthreads();
            if (s + 1 < S_) p0 = __ldg(ebase + (size_t)(s + 1) * 512 + tid);
            float e = 0.f;
#pragma unroll
            for (int i = 0; i < 16; i++) {
                int h = lane + 32 * i;
                e = fmaf(vsh[h], ftanh(row[h] + df[w][h]), e);
            }
#pragma unroll
            for (int off = 16; off; off >>= 1) e += __shfl_xor_sync(0xffffffffu, e, off);
            if (lane == 0) {
                e += vbv;
                if (mask[b * S_ + s]) e = -1e9f;
                en[w][s] = e;
            }
            __syncthreads();
        }
    }

    // softmax (warp w handles t0+w)
    {
        float vals[4];
        float m = -1e30f;
#pragma unroll
        for (int i = 0; i < 4; i++) { vals[i] = en[w][lane + 32 * i]; m = fmaxf(m, vals[i]); }
#pragma unroll
        for (int off = 16; off; off >>= 1) m = fmaxf(m, __shfl_xor_sync(0xffffffffu, m, off));
        float ssum = 0.f;
#pragma unroll
        for (int i = 0; i < 4; i++) { vals[i] = __expf(vals[i] - m); ssum += vals[i]; }
#pragma unroll
        for (int off = 16; off; off >>= 1) ssum += __shfl_xor_sync(0xffffffffu, ssum, off);
        float inv = 1.f / ssum;
#pragma unroll
        for (int i = 0; i < 4; i++) en[w][lane + 32 * i] = vals[i] * inv;
    }
    __syncthreads();

    // phase 2: context — thread owns column tid, 16 t accumulators
    float cacc[16];
#pragma unroll
    for (int jj = 0; jj < 16; jj++) cacc[jj] = 0.f;
    {
        const float* mbase = mem + (size_t)(b * S_) * 512;
        float q0 = __ldg(mbase + tid);
        for (int s = 0; s < S_; s++) {
            row[tid] = q0;
            __syncthreads();
            if (s + 1 < S_) q0 = __ldg(mbase + (size_t)(s + 1) * 512 + tid);
            float m0 = row[tid];
#pragma unroll
            for (int jj = 0; jj < 16; jj++)
                cacc[jj] = fmaf(en[jj][s], m0, cacc[jj]);
            __syncthreads();
        }
    }
#pragma unroll
    for (int jj = 0; jj < 16; jj++) {
        outcat[((size_t)(b * T_ + t0 + jj)) * 1024 + 512 + tid] = cacc[jj];
    }
}

// ---------------- launch -------------------------------------------------------
extern "C" void kernel_launch(void* const* d_in, const int* in_sizes, int n_in,
                              void* d_out, int out_size) {
    (void)in_sizes; (void)n_in; (void)out_size;
    const int*   tgt  = (const int*)d_in[0];
    const float* mem  = (const float*)d_in[1];
    const unsigned char* mask = (const unsigned char*)d_in[2];
    const float* emb  = (const float*)d_in[3];
    const float* Wih0 = (const float*)d_in[4];
    const float* Whh0 = (const float*)d_in[5];
    const float* bih0 = (const float*)d_in[6];
    const float* bhh0 = (const float*)d_in[7];
    const float* Wih1 = (const float*)d_in[8];
    const float* Whh1 = (const float*)d_in[9];
    const float* bih1 = (const float*)d_in[10];
    const float* bhh1 = (const float*)d_in[11];
    const float* Wh   = (const float*)d_in[12];
    const float* bh   = (const float*)d_in[13];
    const float* Ws   = (const float*)d_in[14];
    const float* bs   = (const float*)d_in[15];
    const float* v    = (const float*)d_in[16];
    const float* vb   = (const float*)d_in[17];
    const float* Wout = (const float*)d_in[18];
    const float* bout = (const float*)d_in[19];

    float* out = (float*)d_out;
    float* logits = out;
    float* hn = out + (size_t)B_ * T_ * V_;
    float* cn = hn + 2 * B_ * H_;

    float *px, *pgates, *pcat, *pencf, *pdecf, *pench;
    float *ph0a, *ph0b, *ph1a, *ph1b, *py1a, *py1b;
    cudaGetSymbolAddress((void**)&px, g_x);
    cudaGetSymbolAddress((void**)&pgates, g_gates);
    cudaGetSymbolAddress((void**)&pcat, g_cat);
    cudaGetSymbolAddress((void**)&pencf, g_encf);
    cudaGetSymbolAddress((void**)&pdecf, g_decf);
    cudaGetSymbolAddress((void**)&pench, g_ench_t);
    cudaGetSymbolAddress((void**)&ph0a, g_h0a);
    cudaGetSymbolAddress((void**)&ph0b, g_h0b);
    cudaGetSymbolAddress((void**)&ph1a, g_h1a);
    cudaGetSymbolAddress((void**)&ph1b, g_h1b);
    cudaGetSymbolAddress((void**)&py1a, g_y1a);
    cudaGetSymbolAddress((void**)&py1b, g_y1b);

    cudaFuncSetAttribute(k_lstm2, cudaFuncAttributeMaxDynamicSharedMemorySize, LSTM_SMEM);
    cudaFuncSetAttribute(gemm_tf32, cudaFuncAttributeMaxDynamicSharedMemorySize, GEMM_SMEM);

    // 1. embedding + enc_hidden (transposed)
    k_embed<<<2048, 128>>>(tgt, emb, px);
    k_mean<<<B_, 512>>>(mem, pench);

    // 2. attention enc features (independent of LSTM)
    gemm_tf32<<<dim3(4, 16), 256, GEMM_SMEM>>>(mem, 512, Wh, 512, 512, bh, nullptr, pencf, 512);

    // 3. layer0 input gates (tf32 mma)
    gemm_tf32<<<dim3(16, 16), 256, GEMM_SMEM>>>(px, 512, Wih0, 512, 512, bih0, bhh0, pgates, 2048);

    // 4. fused pipelined 2-layer LSTM (y2 -> first half of g_cat)
    k_lstm2<<<TOT_CTAS, LSTM_THREADS, LSTM_SMEM>>>(
        pgates, Whh0, Wih1, Whh1, bih1, bhh1, pench,
        pcat, hn, cn, ph0a, ph0b, ph1a, ph1b, py1a, py1b);

    // 5. dec features
    gemm_tf32<<<dim3(4, 16), 256, GEMM_SMEM>>>(pcat, 1024, Ws, 512, 512, bs, nullptr, pdecf, 512);

    // 6. fused energy/softmax/context -> second half of g_cat
    k_attn<<<dim3(B_, T_ / 16), 512>>>(pencf, pdecf, mem, mask, v, vb, pcat);

    // 7. output projection (tf32 mma)
    gemm_tf32<<<dim3(32, 16), 256, GEMM_SMEM>>>(pcat, 1024, Wout, 1024, 1024, bout, nullptr, logits, 4096);
}

// round 16
// speedup vs baseline: 1.2760x; 1.0103x over previous
#include <cuda_runtime.h>
#include <math.h>
#include <stdint.h>

#define B_ 16
#define T_ 128
#define S_ 128
#define E_ 512
#define H_ 512
#define V_ 4096

#define TOT_CTAS 128               // 64 CTAs per layer
#define LSTM_THREADS 256
// dynamic smem: hs 32KB + xs 32KB + pr 17408
#define LSTM_SMEM (32768 + 32768 + 17408)

#define GEMM_BUF_FLOATS (128 * 20)
#define GEMM_SMEM (6 * GEMM_BUF_FLOATS * 4)   // 3-stage ring for A and B
#define GEMM_MAX_CTAS 296                      // 148 SMs x 2 CTAs

// ---------------- scratch (device globals; no cudaMalloc allowed) -------------
__device__ float g_x[2048 * 512];        // embedded input [B*T, E]
__device__ float g_gates[2048 * 2048];   // precomputed layer0 input gates [B*T, 4H]
__device__ float g_cat[2048 * 1024];     // [y2 | context]  [B*T, H+E]
__device__ float g_encf[2048 * 512];     // enc_feat [B*S, H]
__device__ float g_decf[2048 * 512];     // dec_feat [B*T, H]
__device__ float g_ench_t[512 * 16];     // enc_hidden TRANSPOSED [k][b]
__device__ float g_h0a[512 * 16];
__device__ float g_h0b[512 * 16];
__device__ float g_h1a[512 * 16];
__device__ float g_h1b[512 * 16];
__device__ float g_y1a[512 * 16];
__device__ float g_y1b[512 * 16];
__device__ unsigned long long g_bar_cnt;

// ---------------- fast activations (single-MUFU tanh.approx) -------------------
__device__ __forceinline__ float ftanh(float x) {
    float y; asm("tanh.approx.f32 %0, %1;" : "=f"(y) : "f"(x)); return y;
}
__device__ __forceinline__ float fsig(float x) {
    return 0.5f * ftanh(0.5f * x) + 0.5f;
}

// ---------------- grid barrier (release/acquire, tight spin on tid0) ----------
__device__ __forceinline__ void grid_barrier() {
    __syncthreads();
    if (threadIdx.x == 0) {
        unsigned long long old, cur;
        asm volatile("atom.add.release.gpu.u64 %0, [%1], 1;"
                     : "=l"(old) : "l"(&g_bar_cnt) : "memory");
        unsigned long long target = (old / TOT_CTAS + 1ULL) * TOT_CTAS;
        do {
            asm volatile("ld.acquire.gpu.u64 %0, [%1];"
                         : "=l"(cur) : "l"(&g_bar_cnt) : "memory");
        } while (cur < target);
    }
    __syncthreads();
}

// ---------------- embedding gather --------------------------------------------
__global__ void k_embed(const int* __restrict__ tgt, const float* __restrict__ emb,
                        float* __restrict__ x) {
    int r = blockIdx.x;
    int tok = tgt[r];
    ((float4*)x)[r * 128 + threadIdx.x] = ((const float4*)emb)[tok * 128 + threadIdx.x];
}

// ---------------- mean over source positions (writes TRANSPOSED [e][b]) -------
__global__ void k_mean(const float* __restrict__ mem, float* __restrict__ out_t) {
    int b = blockIdx.x;
    int e = threadIdx.x;
    float s = 0.f;
    for (int t = 0; t < S_; t++) s += mem[(b * S_ + t) * 512 + e];
    out_t[e * 16 + b] = s * (1.f / (float)S_);
}

// ---------------- tf32 helpers --------------------------------------------------
__device__ __forceinline__ uint32_t f2tf32(float f) {
    uint32_t u; asm("cvt.rna.tf32.f32 %0, %1;" : "=r"(u) : "f"(f)); return u;
}
__device__ __forceinline__ void mma_tf32(float* d, const uint32_t* a, const uint32_t* b) {
    asm volatile("mma.sync.aligned.m16n8k8.row.col.f32.tf32.tf32.f32 "
        "{%0,%1,%2,%3}, {%4,%5,%6,%7}, {%8,%9}, {%0,%1,%2,%3};"
        : "+f"(d[0]), "+f"(d[1]), "+f"(d[2]), "+f"(d[3])
        : "r"(a[0]), "r"(a[1]), "r"(a[2]), "r"(a[3]), "r"(b[0]), "r"(b[1]));
}
__device__ __forceinline__ uint32_t smem_u32(const void* p) {
    uint32_t a;
    asm("{ .reg .u64 t; cvta.to.shared.u64 t, %1; cvt.u32.u64 %0, t; }"
        : "=r"(a) : "l"(p));
    return a;
}
#define CP16(dst, src) \
    asm volatile("cp.async.cg.shared.global [%0], [%1], 16;" :: "r"(dst), "l"(src))
#define CP_COMMIT() asm volatile("cp.async.commit_group;" ::: "memory")
#define CP_WAIT1()  asm volatile("cp.async.wait_group 1;" ::: "memory")
#define CP_WAIT0()  asm volatile("cp.async.wait_group 0;" ::: "memory")

// ---------------- persistent multi-problem tf32 GEMM ---------------------------
struct GemmP {
    const float* A; const float* W; const float* b1; const float* b2; float* C;
    int lda, ldw, K, ldc, tilesx, tiles;
};

__global__ __launch_bounds__(256, 2) void gemm_tf32(GemmP p0, GemmP p1, int nprob) {
    extern __shared__ float gshm[];
    float* As = gshm;                              // [3][GEMM_BUF_FLOATS]
    float* Bs = gshm + 3 * GEMM_BUF_FLOATS;        // [3][GEMM_BUF_FLOATS]
    const int tid = threadIdx.x;
    const int warp = tid >> 5, lane = tid & 31;
    const int wm = (warp & 1) * 64;
    const int wn = (warp >> 1) * 32;
    const int g = lane >> 2, c = lane & 3;
    const int lr = tid >> 2;
    const int lq = tid & 3;

    const uint32_t sA0 = smem_u32(&As[lr * 20 + lq * 4]);
    const uint32_t sA1 = smem_u32(&As[(lr + 64) * 20 + lq * 4]);
    const uint32_t sB0 = smem_u32(&Bs[lr * 20 + lq * 4]);
    const uint32_t sB1 = smem_u32(&Bs[(lr + 64) * 20 + lq * 4]);
    const uint32_t bufbytes = GEMM_BUF_FLOATS * 4;

    const int total = p0.tiles + (nprob > 1 ? p1.tiles : 0);

    for (int tl = blockIdx.x; tl < total; tl += gridDim.x) {
        const bool first = (tl < p0.tiles);
        const GemmP& p = first ? p0 : p1;
        const int lt = first ? tl : tl - p0.tiles;
        const int m0 = (lt / p.tilesx) * 128;
        const int n0 = (lt % p.tilesx) * 128;

        const float* Ap = p.A + (size_t)(m0 + lr) * p.lda + lq * 4;
        const float* Wp = p.W + (size_t)(n0 + lr) * p.ldw + lq * 4;
        const size_t astep = (size_t)64 * p.lda;
        const size_t wstep = (size_t)64 * p.ldw;

        float acc[4][4][4];
#pragma unroll
        for (int i = 0; i < 4; i++)
#pragma unroll
            for (int j = 0; j < 4; j++)
#pragma unroll
                for (int q = 0; q < 4; q++) acc[i][j][q] = 0.f;

        __syncthreads();   // protect smem from previous tile's readers

        const int nkt = p.K >> 4;
        {
            CP16(sA0, Ap); CP16(sA1, Ap + astep);
            CP16(sB0, Wp); CP16(sB1, Wp + wstep);
            CP_COMMIT();
            const float* Ap2 = Ap + 16;
            const float* Wp2 = Wp + 16;
            CP16(sA0 + bufbytes, Ap2); CP16(sA1 + bufbytes, Ap2 + astep);
            CP16(sB0 + bufbytes, Wp2); CP16(sB1 + bufbytes, Wp2 + wstep);
            CP_COMMIT();
        }

        for (int kt = 0; kt < nkt; kt++) {
            if (kt + 1 < nkt) { CP_WAIT1(); } else { CP_WAIT0(); }
            __syncthreads();
            if (kt + 2 < nkt) {
                const uint32_t off = ((kt + 2) % 3) * bufbytes;
                const float* Ap2 = Ap + (kt + 2) * 16;
                const float* Wp2 = Wp + (kt + 2) * 16;
                CP16(sA0 + off, Ap2); CP16(sA1 + off, Ap2 + astep);
                CP16(sB0 + off, Wp2); CP16(sB1 + off, Wp2 + wstep);
                CP_COMMIT();
            }

            const float* Ab = As + (kt % 3) * GEMM_BUF_FLOATS;
            const float* Bb = Bs + (kt % 3) * GEMM_BUF_FLOATS;
#pragma unroll
            for (int kk = 0; kk < 16; kk += 8) {
                uint32_t af[4][4];
                uint32_t bf[4][2];
#pragma unroll
                for (int mt = 0; mt < 4; mt++) {
                    int mr = wm + mt * 16 + g;
                    af[mt][0] = __float_as_uint(Ab[mr * 20 + kk + c]);
                    af[mt][1] = __float_as_uint(Ab[(mr + 8) * 20 + kk + c]);
                    af[mt][2] = __float_as_uint(Ab[mr * 20 + kk + c + 4]);
                    af[mt][3] = __float_as_uint(Ab[(mr + 8) * 20 + kk + c + 4]);
                }
#pragma unroll
                for (int nt = 0; nt < 4; nt++) {
                    int nr = wn + nt * 8 + g;
                    bf[nt][0] = __float_as_uint(Bb[nr * 20 + kk + c]);
                    bf[nt][1] = __float_as_uint(Bb[nr * 20 + kk + c + 4]);
                }
#pragma unroll
                for (int mt = 0; mt < 4; mt++)
#pragma unroll
                    for (int nt = 0; nt < 4; nt++)
                        mma_tf32(acc[mt][nt], af[mt], bf[nt]);
            }
        }

        float bv0[4], bv1[4];
#pragma unroll
        for (int nt = 0; nt < 4; nt++) {
            int col = n0 + wn + nt * 8 + 2 * c;
            float x0 = p.b1 ? __ldg(&p.b1[col]) : 0.f;
            float x1 = p.b1 ? __ldg(&p.b1[col + 1]) : 0.f;
            if (p.b2) { x0 += __ldg(&p.b2[col]); x1 += __ldg(&p.b2[col + 1]); }
            bv0[nt] = x0; bv1[nt] = x1;
        }
#pragma unroll
        for (int mt = 0; mt < 4; mt++) {
            int r0 = m0 + wm + mt * 16 + g;
#pragma unroll
            for (int nt = 0; nt < 4; nt++) {
                int col = n0 + wn + nt * 8 + 2 * c;
                float2 o0 = make_float2(acc[mt][nt][0] + bv0[nt], acc[mt][nt][1] + bv1[nt]);
                float2 o1 = make_float2(acc[mt][nt][2] + bv0[nt], acc[mt][nt][3] + bv1[nt]);
                *(float2*)&p.C[(size_t)r0 * p.ldc + col] = o0;
                *(float2*)&p.C[(size_t)(r0 + 8) * p.ldc + col] = o1;
            }
        }
    }
}

// ---------------- fused 2-layer pipelined persistent LSTM ----------------------
__global__ __launch_bounds__(LSTM_THREADS, 1) void k_lstm2(
    const float* __restrict__ gates0,
    const float* __restrict__ Whh0,
    const float* __restrict__ Wih1,
    const float* __restrict__ Whh1,
    const float* __restrict__ bih1, const float* __restrict__ bhh1,
    const float* __restrict__ h_init_t,
    float* __restrict__ ycat,
    float* __restrict__ hn, float* __restrict__ cn,
    float* __restrict__ h0a, float* __restrict__ h0b,
    float* __restrict__ h1a, float* __restrict__ h1b,
    float* __restrict__ y1a, float* __restrict__ y1b) {
    extern __shared__ float smf[];
    float* hs = smf;
    float* xs = smf + 512 * 16;
    float (*pr)[32][17] = (float(*)[32][17])(smf + 2 * 512 * 16);

    const int tid = threadIdx.x;
    const int layer = blockIdx.x >> 6;
    const int bidx = blockIdx.x & 63;
    const int w = tid >> 5, lane = tid & 31;
    const int g = lane >> 2, c = lane & 3;
    const uint32_t* hsu = (const uint32_t*)hs;
    const uint32_t* xsu = (const uint32_t*)xs;
    const uint32_t hs_base = smem_u32(hs);
    const uint32_t xs_base = smem_u32(xs);

    uint32_t afr_h[2][8][4];
    uint32_t afr_x[2][8][4];
    {
        const float* Wh_ = layer ? Whh1 : Whh0;
#pragma unroll
        for (int tau = 0; tau < 2; tau++) {
            int ng0 = (g >> 2) * 512 + bidx * 8 + tau * 4 + (g & 3);
            int ng1 = ((g + 8) >> 2) * 512 + bidx * 8 + tau * 4 + (g & 3);
            const float* w0 = Wh_ + (size_t)ng0 * 512;
            const float* w1 = Wh_ + (size_t)ng1 * 512;
#pragma unroll
            for (int kc = 0; kc < 8; kc++) {
                int kb = w * 64 + kc * 8;
                afr_h[tau][kc][0] = f2tf32(__ldg(w0 + kb + c));
                afr_h[tau][kc][1] = f2tf32(__ldg(w1 + kb + c));
                afr_h[tau][kc][2] = f2tf32(__ldg(w0 + kb + c + 4));
                afr_h[tau][kc][3] = f2tf32(__ldg(w1 + kb + c + 4));
            }
            if (layer) {
                const float* x0 = Wih1 + (size_t)ng0 * 512;
                const float* x1 = Wih1 + (size_t)ng1 * 512;
#pragma unroll
                for (int kc = 0; kc < 8; kc++) {
                    int kb = w * 64 + kc * 8;
                    afr_x[tau][kc][0] = f2tf32(__ldg(x0 + kb + c));
                    afr_x[tau][kc][1] = f2tf32(__ldg(x1 + kb + c));
                    afr_x[tau][kc][2] = f2tf32(__ldg(x0 + kb + c + 4));
                    afr_x[tau][kc][3] = f2tf32(__ldg(x1 + kb + c + 4));
                }
            }
        }
    }

    float c_reg = 0.f;
    const int cb = tid & 15, hloc = (tid >> 4) & 7;
    const int kh = bidx * 8 + hloc;
    const int ctau = hloc >> 2, cr = hloc & 3;
    float gp[4] = {0.f, 0.f, 0.f, 0.f};
    if (tid < 128) {
        if (layer) {
#pragma unroll
            for (int g4 = 0; g4 < 4; g4++)
                gp[g4] = __ldg(&bih1[g4 * 512 + kh]) + __ldg(&bhh1[g4 * 512 + kh]);
        } else {
            const float* gpr = gates0 + ((size_t)(cb * T_)) * 2048 + kh;
#pragma unroll
            for (int g4 = 0; g4 < 4; g4++)
                gp[g4] = __ldg(gpr + g4 * 512);
        }
    }

    grid_barrier();

    for (int s = 0; s <= T_; s++) {
        const int t = layer ? (s - 1) : s;
        const bool active = layer ? (s >= 1) : (s < T_);
        if (active) {
            const float* hin;
            float* hout;
            if (layer == 0) {
                hin  = (t == 0) ? h_init_t : ((t & 1) ? h0a : h0b);
                hout = (t & 1) ? h0b : h0a;
            } else {
                hin  = (t == 0) ? h_init_t : ((t & 1) ? h1a : h1b);
                hout = (t & 1) ? h1b : h1a;
            }
            const float* xin = (t & 1) ? y1b : y1a;
            float* yout = (t & 1) ? y1b : y1a;

#pragma unroll
            for (int i = 0; i < 8; i++) {
                int idx = tid + 256 * i;
                CP16(hs_base + idx * 16, ((const float4*)hin) + idx);
            }
            if (layer) {
#pragma unroll
                for (int i = 0; i < 8; i++) {
                    int idx = tid + 256 * i;
                    CP16(xs_base + idx * 16, ((const float4*)xin) + idx);
                }
            }
            CP_COMMIT();
            CP_WAIT0();
            __syncthreads();

            float acc[2][2][4];
#pragma unroll
            for (int a = 0; a < 2; a++)
#pragma unroll
                for (int b = 0; b < 2; b++)
#pragma unroll
                    for (int q = 0; q < 4; q++) acc[a][b][q] = 0.f;

#pragma unroll
            for (int kc = 0; kc < 8; kc++) {
                int kb = w * 64 + kc * 8;
                uint32_t b0[2], b1[2];
                b0[0] = hsu[(kb + c) * 16 + g];
                b0[1] = hsu[(kb + c + 4) * 16 + g];
                b1[0] = hsu[(kb + c) * 16 + 8 + g];
                b1[1] = hsu[(kb + c + 4) * 16 + 8 + g];
                mma_tf32(acc[0][0], afr_h[0][kc], b0);
                mma_tf32(acc[0][1], afr_h[0][kc], b1);
                mma_tf32(acc[1][0], afr_h[1][kc], b0);
                mma_tf32(acc[1][1], afr_h[1][kc], b1);
            }
            if (layer) {
#pragma unroll
                for (int kc = 0; kc < 8; kc++) {
                    int kb = w * 64 + kc * 8;
                    uint32_t b0[2], b1[2];
                    b0[0] = xsu[(kb + c) * 16 + g];
                    b0[1] = xsu[(kb + c + 4) * 16 + g];
                    b1[0] = xsu[(kb + c) * 16 + 8 + g];
                    b1[1] = xsu[(kb + c + 4) * 16 + 8 + g];
                    mma_tf32(acc[0][0], afr_x[0][kc], b0);
                    mma_tf32(acc[0][1], afr_x[0][kc], b1);
                    mma_tf32(acc[1][0], afr_x[1][kc], b0);
                    mma_tf32(acc[1][1], afr_x[1][kc], b1);
                }
            }
#pragma unroll
            for (int tau = 0; tau < 2; tau++) {
                pr[w][tau * 16 + g][2 * c]         = acc[tau][0][0];
                pr[w][tau * 16 + g][2 * c + 1]     = acc[tau][0][1];
                pr[w][tau * 16 + g + 8][2 * c]     = acc[tau][0][2];
                pr[w][tau * 16 + g + 8][2 * c + 1] = acc[tau][0][3];
                pr[w][tau * 16 + g][8 + 2 * c]         = acc[tau][1][0];
                pr[w][tau * 16 + g][8 + 2 * c + 1]     = acc[tau][1][1];
                pr[w][tau * 16 + g + 8][8 + 2 * c]     = acc[tau][1][2];
                pr[w][tau * 16 + g + 8][8 + 2 * c + 1] = acc[tau][1][3];
            }
            __syncthreads();

            if (tid < 128) {
                float sg[4];
#pragma unroll
                for (int g4 = 0; g4 < 4; g4++) {
                    float a = gp[g4];
                    int row = ctau * 16 + g4 * 4 + cr;
#pragma unroll
                    for (int q = 0; q < 8; q++) a += pr[q][row][cb];
                    sg[g4] = a;
                }
                float iv = fsig(sg[0]);
                float fv = fsig(sg[1]);
                float gv = ftanh(sg[2]);
                float ov = fsig(sg[3]);
                c_reg = fv * c_reg + iv * gv;
                float hv = ov * ftanh(c_reg);
                hout[kh * 16 + cb] = hv;
                if (layer == 0) {
                    yout[kh * 16 + cb] = hv;
                    if (t == T_ - 1) {
                        hn[cb * 512 + kh] = hv;
                        cn[cb * 512 + kh] = c_reg;
                    }
                    if (t + 1 < T_) {
                        const float* gpr = gates0 + ((size_t)(cb * T_ + t + 1)) * 2048 + kh;
#pragma unroll
                        for (int g4 = 0; g4 < 4; g4++)
                            gp[g4] = __ldg(gpr + g4 * 512);
                    }
                } else {
                    ycat[((size_t)(cb * T_ + t)) * 1024 + kh] = hv;
                    if (t == T_ - 1) {
                        hn[B_ * H_ + cb * 512 + kh] = hv;
                        cn[B_ * H_ + cb * 512 + kh] = c_reg;
                    }
                }
            }
        }
        grid_barrier();
    }
}

// ---------------- fused attention (t-tile 16, 512 threads, prefetch rows) ------
__global__ __launch_bounds__(512) void k_attn(
    const float* __restrict__ encf, const float* __restrict__ decf,
    const float* __restrict__ mem, const unsigned char* __restrict__ mask,
    const float* __restrict__ v, const float* __restrict__ vb,
    float* __restrict__ outcat) {
    __shared__ float df[16][512];
    __shared__ float vsh[512];
    __shared__ float row[512];
    __shared__ float en[16][128];
    const int b = blockIdx.x;
    const int t0 = blockIdx.y * 16;
    const int tid = threadIdx.x;
    const int w = tid >> 5, lane = tid & 31;

    for (int i = tid; i < 512; i += 512) vsh[i] = v[i];
    for (int i = tid; i < 16 * 512; i += 512) {
        int jj = i >> 9, h = i & 511;
        df[jj][h] = decf[((size_t)(b * T_ + t0 + jj)) * 512 + h];
    }
    __syncthreads();
    const float vbv = vb[0];

    {
        const float* ebase = encf + (size_t)(b * S_) * 512;
        float p0 = __ldg(ebase + tid);
        for (int s = 0; s < S_; s++) {
            row[tid] = p0;
            __syncthreads();
            if (s + 1 < S_) p0 = __ldg(ebase + (size_t)(s + 1) * 512 + tid);
            float e = 0.f;
#pragma unroll
            for (int i = 0; i < 16; i++) {
                int h = lane + 32 * i;
                e = fmaf(vsh[h], ftanh(row[h] + df[w][h]), e);
            }
#pragma unroll
            for (int off = 16; off; off >>= 1) e += __shfl_xor_sync(0xffffffffu, e, off);
            if (lane == 0) {
                e += vbv;
                if (mask[b * S_ + s]) e = -1e9f;
                en[w][s] = e;
            }
            __syncthreads();
        }
    }

    {
        float vals[4];
        float m = -1e30f;
#pragma unroll
        for (int i = 0; i < 4; i++) { vals[i] = en[w][lane + 32 * i]; m = fmaxf(m, vals[i]); }
#pragma unroll
        for (int off = 16; off; off >>= 1) m = fmaxf(m, __shfl_xor_sync(0xffffffffu, m, off));
        float ssum = 0.f;
#pragma unroll
        for (int i = 0; i < 4; i++) { vals[i] = __expf(vals[i] - m); ssum += vals[i]; }
#pragma unroll
        for (int off = 16; off; off >>= 1) ssum += __shfl_xor_sync(0xffffffffu, ssum, off);
        float inv = 1.f / ssum;
#pragma unroll
        for (int i = 0; i < 4; i++) en[w][lane + 32 * i] = vals[i] * inv;
    }
    __syncthreads();

    float cacc[16];
#pragma unroll
    for (int jj = 0; jj < 16; jj++) cacc[jj] = 0.f;
    {
        const float* mbase = mem + (size_t)(b * S_) * 512;
        float q0 = __ldg(mbase + tid);
        for (int s = 0; s < S_; s++) {
            row[tid] = q0;
            __syncthreads();
            if (s + 1 < S_) q0 = __ldg(mbase + (size_t)(s + 1) * 512 + tid);
            float m0 = row[tid];
#pragma unroll
            for (int jj = 0; jj < 16; jj++)
                cacc[jj] = fmaf(en[jj][s], m0, cacc[jj]);
            __syncthreads();
        }
    }
#pragma unroll
    for (int jj = 0; jj < 16; jj++) {
        outcat[((size_t)(b * T_ + t0 + jj)) * 1024 + 512 + tid] = cacc[jj];
    }
}

// ---------------- launch -------------------------------------------------------
extern "C" void kernel_launch(void* const* d_in, const int* in_sizes, int n_in,
                              void* d_out, int out_size) {
    (void)in_sizes; (void)n_in; (void)out_size;
    const int*   tgt  = (const int*)d_in[0];
    const float* mem  = (const float*)d_in[1];
    const unsigned char* mask = (const unsigned char*)d_in[2];
    const float* emb  = (const float*)d_in[3];
    const float* Wih0 = (const float*)d_in[4];
    const float* Whh0 = (const float*)d_in[5];
    const float* bih0 = (const float*)d_in[6];
    const float* bhh0 = (const float*)d_in[7];
    const float* Wih1 = (const float*)d_in[8];
    const float* Whh1 = (const float*)d_in[9];
    const float* bih1 = (const float*)d_in[10];
    const float* bhh1 = (const float*)d_in[11];
    const float* Wh   = (const float*)d_in[12];
    const float* bh   = (const float*)d_in[13];
    const float* Ws   = (const float*)d_in[14];
    const float* bs   = (const float*)d_in[15];
    const float* v    = (const float*)d_in[16];
    const float* vb   = (const float*)d_in[17];
    const float* Wout = (const float*)d_in[18];
    const float* bout = (const float*)d_in[19];

    float* out = (float*)d_out;
    float* logits = out;
    float* hn = out + (size_t)B_ * T_ * V_;
    float* cn = hn + 2 * B_ * H_;

    float *px, *pgates, *pcat, *pencf, *pdecf, *pench;
    float *ph0a, *ph0b, *ph1a, *ph1b, *py1a, *py1b;
    cudaGetSymbolAddress((void**)&px, g_x);
    cudaGetSymbolAddress((void**)&pgates, g_gates);
    cudaGetSymbolAddress((void**)&pcat, g_cat);
    cudaGetSymbolAddress((void**)&pencf, g_encf);
    cudaGetSymbolAddress((void**)&pdecf, g_decf);
    cudaGetSymbolAddress((void**)&pench, g_ench_t);
    cudaGetSymbolAddress((void**)&ph0a, g_h0a);
    cudaGetSymbolAddress((void**)&ph0b, g_h0b);
    cudaGetSymbolAddress((void**)&ph1a, g_h1a);
    cudaGetSymbolAddress((void**)&ph1b, g_h1b);
    cudaGetSymbolAddress((void**)&py1a, g_y1a);
    cudaGetSymbolAddress((void**)&py1b, g_y1b);

    cudaFuncSetAttribute(k_lstm2, cudaFuncAttributeMaxDynamicSharedMemorySize, LSTM_SMEM);
    cudaFuncSetAttribute(gemm_tf32, cudaFuncAttributeMaxDynamicSharedMemorySize, GEMM_SMEM);

    GemmP pEncf = { mem, Wh, bh, nullptr, pencf, 512, 512, 512, 512, 4, 64 };
    GemmP pGates = { px, Wih0, bih0, bhh0, pgates, 512, 512, 512, 2048, 16, 256 };
    GemmP pDecf = { pcat, Ws, bs, nullptr, pdecf, 1024, 512, 512, 512, 4, 64 };
    GemmP pLogits = { pcat, Wout, bout, nullptr, logits, 1024, 1024, 1024, 4096, 32, 512 };
    GemmP pNull = {};

    // 1. embedding + enc_hidden (transposed)
    k_embed<<<2048, 128>>>(tgt, emb, px);
    k_mean<<<B_, 512>>>(mem, pench);

    // 2. fused encf + gates0 (one persistent launch fills the machine)
    gemm_tf32<<<GEMM_MAX_CTAS, 256, GEMM_SMEM>>>(pEncf, pGates, 2);

    // 3. fused pipelined 2-layer LSTM (y2 -> first half of g_cat)
    k_lstm2<<<TOT_CTAS, LSTM_THREADS, LSTM_SMEM>>>(
        pgates, Whh0, Wih1, Whh1, bih1, bhh1, pench,
        pcat, hn, cn, ph0a, ph0b, ph1a, ph1b, py1a, py1b);

    // 4. dec features
    gemm_tf32<<<64, 256, GEMM_SMEM>>>(pDecf, pNull, 1);

    // 5. fused energy/softmax/context -> second half of g_cat
    k_attn<<<dim3(B_, T_ / 16), 512>>>(pencf, pdecf, mem, mask, v, vb, pcat);

    // 6. output projection (persistent, wave-balanced)
    gemm_tf32<<<GEMM_MAX_CTAS, 256, GEMM_SMEM>>>(pLogits, pNull, 1);
}